// round 1
// baseline (speedup 1.0000x reference)
#include <cuda_runtime.h>

// SMFNet: chord-masked iterative mixing, fully fused.
// B=2, N=8192, D=64, DV=64, M=3.
// mask = diag + (i, (i+1)%N)  =>  per-iter: V'[i] = a_i V[i] + c_i V[i+1]
// Unrolled over M=3:
//   V3[i] = (w0 X[i] + w1 X[i+1] + w2 X[i+2] + w3 X[i+3]) @ Wg + (w0+w1+w2+w3) * bg
// with
//   w0 = A3 A2_i A1_i
//   w1 = A3 (A2_i C1_i + C2_i A1_{i+1}) + C3 A2_{i+1} A1_{i+1}
//   w2 = A3 C2_i C1_{i+1} + C3 (A2_{i+1} C1_{i+1} + C2_{i+1} A1_{i+2})
//   w3 = C3 C2_{i+1} C1_{i+2}
// where Am_j = X[j]·Wf[m][:,j] + bf[m][j], Cm_j = X[j]·Wf[m][:,j+1] + bf[m][j+1].

#define Bc   2
#define Nc   8192
#define Dc   64
#define DVc  64
#define TROWS 128        // output rows per block
#define XR    132        // X rows staged (need TROWS+3 = 131)
#define NTHREADS 256

// dynamic smem layout (floats)
#define OFF_XS    0                       // XR * 65  (pad 65: conflict-free column walks)
#define OFF_WGS   (OFF_XS  + XR*65)       // 64 * 64  (stride 64: float4-aligned)
#define OFF_XWS   (OFF_WGS + 64*64)       // TROWS * 65
#define OFF_AS    (OFF_XWS + TROWS*65)    // 3 * XR
#define OFF_CS    (OFF_AS  + 3*XR)        // 3 * XR
#define OFF_WC    (OFF_CS  + 3*XR)        // TROWS * 4
#define OFF_WSUM  (OFF_WC  + TROWS*4)     // TROWS
#define OFF_BGS   (OFF_WSUM + TROWS)      // 64
#define SMEM_FLOATS (OFF_BGS + 64)
#define SMEM_BYTES (SMEM_FLOATS * 4)

__global__ __launch_bounds__(NTHREADS, 1)
void smf_fused_kernel(const float* __restrict__ X,
                      const float* __restrict__ Wg,
                      const float* __restrict__ bg,
                      const float* __restrict__ Wf,
                      const float* __restrict__ bf,
                      float* __restrict__ out)
{
    extern __shared__ float sm[];
    float* Xs   = sm + OFF_XS;
    float* Wgs  = sm + OFF_WGS;
    float* Xws  = sm + OFF_XWS;
    float* As   = sm + OFF_AS;
    float* Cs   = sm + OFF_CS;
    float* Wc   = sm + OFF_WC;
    float* Wsum = sm + OFF_WSUM;
    float* bgs  = sm + OFF_BGS;

    const int t  = threadIdx.x;
    const int b  = blockIdx.y;
    const int r0 = blockIdx.x * TROWS;
    const float* Xb = X + (size_t)b * Nc * Dc;

    // ---- Phase 1: stage Wg, bg, and X rows [r0, r0+131) (wrap mod N) ----
    #pragma unroll 4
    for (int idx = t; idx < 64 * 64; idx += NTHREADS) Wgs[idx] = Wg[idx];
    if (t < 64) bgs[t] = bg[t];
    for (int idx = t; idx < (TROWS + 3) * 64; idx += NTHREADS) {
        int j = idx >> 6, d = idx & 63;
        int gi = (r0 + j) & (Nc - 1);
        Xs[j * 65 + d] = Xb[gi * 64 + d];
    }
    __syncthreads();

    // ---- Phase 2: a/c scalars for rows j = 0..130 ----
    if (t < TROWS + 3) {
        const int j   = t;
        const int gi  = (r0 + j) & (Nc - 1);
        const int gi1 = (gi + 1) & (Nc - 1);
        const float* W0 = Wf;
        const float* W1 = Wf + Dc * Nc;
        const float* W2 = Wf + 2 * Dc * Nc;
        float a0 = 0.f, a1 = 0.f, a2 = 0.f, c0 = 0.f, c1 = 0.f, c2 = 0.f;
        #pragma unroll 4
        for (int d = 0; d < Dc; d++) {
            float xv = Xs[j * 65 + d];
            int o = d * Nc;
            a0 += xv * W0[o + gi];  c0 += xv * W0[o + gi1];
            a1 += xv * W1[o + gi];  c1 += xv * W1[o + gi1];
            a2 += xv * W2[o + gi];  c2 += xv * W2[o + gi1];
        }
        As[0 * XR + j] = a0 + bf[0 * Nc + gi];
        Cs[0 * XR + j] = c0 + bf[0 * Nc + gi1];
        As[1 * XR + j] = a1 + bf[1 * Nc + gi];
        Cs[1 * XR + j] = c1 + bf[1 * Nc + gi1];
        As[2 * XR + j] = a2 + bf[2 * Nc + gi];
        Cs[2 * XR + j] = c2 + bf[2 * Nc + gi1];
    }
    __syncthreads();

    // ---- Phase 3: 4-tap weights per output row ----
    if (t < TROWS) {
        const int j = t;
        float A1i  = As[0 * XR + j], A1i1 = As[0 * XR + j + 1], A1i2 = As[0 * XR + j + 2];
        float C1i  = Cs[0 * XR + j], C1i1 = Cs[0 * XR + j + 1], C1i2 = Cs[0 * XR + j + 2];
        float A2i  = As[1 * XR + j], A2i1 = As[1 * XR + j + 1];
        float C2i  = Cs[1 * XR + j], C2i1 = Cs[1 * XR + j + 1];
        float A3   = As[2 * XR + j], C3   = Cs[2 * XR + j];
        float w0 = A3 * A2i * A1i;
        float w1 = A3 * (A2i * C1i + C2i * A1i1) + C3 * A2i1 * A1i1;
        float w2 = A3 * C2i * C1i1 + C3 * (A2i1 * C1i1 + C2i1 * A1i2);
        float w3 = C3 * C2i1 * C1i2;
        Wc[j * 4 + 0] = w0; Wc[j * 4 + 1] = w1;
        Wc[j * 4 + 2] = w2; Wc[j * 4 + 3] = w3;
        Wsum[j] = w0 + w1 + w2 + w3;
    }
    __syncthreads();

    // ---- Phase 4: combined X rows: Xw[j] = sum_k w_k X[j+k] ----
    #pragma unroll 2
    for (int idx = t; idx < TROWS * 64; idx += NTHREADS) {
        int j = idx >> 6, d = idx & 63;
        float v = Wc[j * 4 + 0] * Xs[ j      * 65 + d]
                + Wc[j * 4 + 1] * Xs[(j + 1) * 65 + d]
                + Wc[j * 4 + 2] * Xs[(j + 2) * 65 + d]
                + Wc[j * 4 + 3] * Xs[(j + 3) * 65 + d];
        Xws[j * 65 + d] = v;
    }
    __syncthreads();

    // ---- Phase 5: matvec Xw @ Wg + wsum*bg ; per-thread 8x4 register tile ----
    {
        const int row_tile = t >> 4;       // 0..15
        const int col_tile = t & 15;       // 0..15
        const int j0 = row_tile * 8;
        const int e0 = col_tile * 4;
        float acc[8][4];
        #pragma unroll
        for (int r = 0; r < 8; r++)
            #pragma unroll
            for (int c = 0; c < 4; c++) acc[r][c] = 0.f;

        #pragma unroll 8
        for (int d = 0; d < Dc; d++) {
            float4 wv = *reinterpret_cast<const float4*>(&Wgs[d * 64 + e0]);
            #pragma unroll
            for (int r = 0; r < 8; r++) {
                float xv = Xws[(j0 + r) * 65 + d];
                acc[r][0] += xv * wv.x;
                acc[r][1] += xv * wv.y;
                acc[r][2] += xv * wv.z;
                acc[r][3] += xv * wv.w;
            }
        }
        #pragma unroll
        for (int r = 0; r < 8; r++) {
            const int j  = j0 + r;
            const int gi = (r0 + j) & (Nc - 1);
            const float ws = Wsum[j];
            float4 o;
            o.x = acc[r][0] + ws * bgs[e0 + 0];
            o.y = acc[r][1] + ws * bgs[e0 + 1];
            o.z = acc[r][2] + ws * bgs[e0 + 2];
            o.w = acc[r][3] + ws * bgs[e0 + 3];
            *reinterpret_cast<float4*>(&out[((size_t)b * Nc + gi) * 64 + e0]) = o;
        }
    }
}

extern "C" void kernel_launch(void* const* d_in, const int* in_sizes, int n_in,
                              void* d_out, int out_size)
{
    const float* X  = (const float*)d_in[0];   // (2, 8192, 64)
    const float* Wg = (const float*)d_in[1];   // (64, 64)
    const float* bg = (const float*)d_in[2];   // (64,)
    const float* Wf = (const float*)d_in[3];   // (3, 64, 8192)
    const float* bf = (const float*)d_in[4];   // (3, 8192)
    float* out = (float*)d_out;                // (2, 8192, 64)

    cudaFuncSetAttribute(smf_fused_kernel,
                         cudaFuncAttributeMaxDynamicSharedMemorySize, SMEM_BYTES);

    dim3 grid(Nc / TROWS, Bc);
    smf_fused_kernel<<<grid, NTHREADS, SMEM_BYTES>>>(X, Wg, bg, Wf, bf, out);
}